// round 9
// baseline (speedup 1.0000x reference)
#include <cuda_runtime.h>
#include <cuda_fp16.h>
#include <cstdint>

#define NN_MAX   100000
#define F        128

// Scratch (fp16): A[n][j] = W1[:,:128]@h[n] + b1 ; B[n][j] = W1[:,128:]@h[n]
__device__ __half g_Ah[NN_MAX * F];
__device__ __half g_Bh[NN_MAX * F];

// Pair-packed fp16 b-fragments for m16n8k16 (row.col):
// entry [ni][kp][lane] (uint4) = { b0(ki=2kp), b1(ki=2kp), b0(ki=2kp+1), b1(ki=2kp+1) }
//   where n = ni*8 + (lane>>2), b0 = h2{W[n][kc+2t],W[n][kc+2t+1]},
//         b1 = h2{W[n][kc+2t+8],W[n][kc+2t+9]}, kc = ki*16, t = lane&3
__device__ uint4 g_W2p[16 * 4 * 32];   // 32 KB
__device__ uint4 g_W1p[32 * 4 * 32];   // 64 KB (256 outs = A||B)

// ---------------------------------------------------------------------------
__device__ __forceinline__ uint32_t h2pack(float lo, float hi) {
    __half2 h = __floats2half2_rn(lo, hi);
    return *reinterpret_cast<uint32_t*>(&h);
}
__device__ __forceinline__ uint32_t h2u(__half2 h) {
    return *reinterpret_cast<uint32_t*>(&h);
}
__device__ __forceinline__ __half2 combh2(uint32_t a, uint32_t b, __half2 m) {
    __half2 ha = *reinterpret_cast<__half2*>(&a);
    __half2 hb = *reinterpret_cast<__half2*>(&b);
    const __half2 z = __float2half2_rn(0.0f);
    return __hmul2(__hmax2(__hadd2(ha, hb), z), m);
}
__device__ __forceinline__ uint32_t smem_u32(const void* p) {
    uint32_t a;
    asm("{ .reg .u64 t; cvta.to.shared.u64 t, %1; cvt.u32.u64 %0, t; }"
        : "=r"(a) : "l"(p));
    return a;
}
__device__ __forceinline__ void cp_async16(uint32_t saddr, const void* gptr) {
    asm volatile("cp.async.ca.shared.global [%0], [%1], 16;"
                 :: "r"(saddr), "l"(gptr));
}

__device__ __forceinline__ void mma_f16(float& c0, float& c1, float& c2, float& c3,
                                        uint32_t a0, uint32_t a1, uint32_t a2, uint32_t a3,
                                        uint32_t b0, uint32_t b1)
{
    asm volatile(
        "mma.sync.aligned.m16n8k16.row.col.f32.f16.f16.f32 "
        "{%0,%1,%2,%3}, {%4,%5,%6,%7}, {%8,%9}, {%0,%1,%2,%3};\n"
        : "+f"(c0), "+f"(c1), "+f"(c2), "+f"(c3)
        : "r"(a0), "r"(a1), "r"(a2), "r"(a3), "r"(b0), "r"(b1));
}

// ===========================================================================
// Prep kernels: pair-packed fragments
// ===========================================================================
__global__ void pack_w2_kernel(const float* __restrict__ W2)
{
    const int idx  = blockIdx.x * blockDim.x + threadIdx.x;   // 0..2047
    if (idx >= 16 * 4 * 32) return;
    const int lane = idx & 31;
    const int kp   = (idx >> 5) & 3;
    const int ni   = idx >> 7;
    const int g    = lane >> 2;
    const int t    = lane & 3;
    const float* w = W2 + (size_t)(ni * 8 + g) * F + kp * 32;
    uint4 q;
    q.x = h2pack(__ldg(&w[2*t]),      __ldg(&w[2*t + 1]));
    q.y = h2pack(__ldg(&w[2*t + 8]),  __ldg(&w[2*t + 9]));
    q.z = h2pack(__ldg(&w[16 + 2*t]),     __ldg(&w[16 + 2*t + 1]));
    q.w = h2pack(__ldg(&w[16 + 2*t + 8]), __ldg(&w[16 + 2*t + 9]));
    g_W2p[idx] = q;
}

__global__ void pack_w1_kernel(const float* __restrict__ W1)
{
    const int idx  = blockIdx.x * blockDim.x + threadIdx.x;   // 0..4095
    if (idx >= 32 * 4 * 32) return;
    const int lane = idx & 31;
    const int kp   = (idx >> 5) & 3;
    const int ni   = idx >> 7;
    const int g    = lane >> 2;
    const int t    = lane & 3;
    const int j2   = ni * 8 + g;
    const float* w = W1 + (size_t)(j2 & 127) * 256 + ((j2 >> 7) << 7) + kp * 32;
    uint4 q;
    q.x = h2pack(__ldg(&w[2*t]),      __ldg(&w[2*t + 1]));
    q.y = h2pack(__ldg(&w[2*t + 8]),  __ldg(&w[2*t + 9]));
    q.z = h2pack(__ldg(&w[16 + 2*t]),     __ldg(&w[16 + 2*t + 1]));
    q.w = h2pack(__ldg(&w[16 + 2*t + 8]), __ldg(&w[16 + 2*t + 9]));
    g_W1p[idx] = q;
}

// ===========================================================================
// fp16 fragment tile layout: tile = mi*8 + ki (mi 0..7, ki 0..7), stride 528 B
// lane (g,t) uint4 = {h2 row(g) k(2t), h2 row(g+8) k(2t),
//                     h2 row(g) k(2t+8), h2 row(g+8) k(2t+8)}
// ===========================================================================
#define XSF_WORDS   (64 * 132)

// ===========================================================================
// Node kernel: [A|B] = h @ W1^T -> fp16 g_Ah/g_Bh
// ===========================================================================
#define NODE_SMEM_B ((XSF_WORDS + 128) * 4 + 16)

__global__ void __launch_bounds__(256, 2)
node_mma_kernel(const float* __restrict__ h,
                const float* __restrict__ b1,
                int n_nodes)
{
    extern __shared__ uint32_t sm[];
    uint32_t* HsF = sm;
    float*    b1s = (float*)(sm + XSF_WORDS);

    const int tid  = threadIdx.x;
    const int lane = tid & 31;
    const int warp = tid >> 5;
    const int g    = lane >> 2;
    const int t    = lane & 3;
    const int base = blockIdx.x * 128;

    if (tid < 128) b1s[tid] = __ldg(&b1[tid]);

    // producer: hoisted loads (8 float4-pairs), then pack + STS
    {
        float4 va[2][4], vb[2][4];        // [p][quarter] row rA / row rB
        int tiles[2];
        float mAs[2], mBs[2];
        #pragma unroll
        for (int p = 0; p < 2; p++) {
            const int tile = p * 32 + warp * 4 + (lane & 3);
            tiles[p] = tile;
            const int gg = lane >> 2;
            const int mi = tile >> 3;
            const int kc = (tile & 7) * 16;
            const int rA = mi * 16 + gg;
            const int rB = rA + 8;
            mAs[p] = ((base + rA) < n_nodes) ? 1.0f : 0.0f;
            mBs[p] = ((base + rB) < n_nodes) ? 1.0f : 0.0f;
            const int nA = ((base + rA) < n_nodes) ? (base + rA) : 0;
            const int nB = ((base + rB) < n_nodes) ? (base + rB) : 0;
            const float4* pa = (const float4*)(h + (size_t)nA * F + kc);
            const float4* pb = (const float4*)(h + (size_t)nB * F + kc);
            #pragma unroll
            for (int q = 0; q < 4; q++) { va[p][q] = __ldg(pa + q); vb[p][q] = __ldg(pb + q); }
        }
        #pragma unroll
        for (int p = 0; p < 2; p++) {
            const int gg = lane >> 2;
            float xA[16], xB[16];
            #pragma unroll
            for (int q = 0; q < 4; q++) {
                xA[q*4+0] = va[p][q].x * mAs[p]; xA[q*4+1] = va[p][q].y * mAs[p];
                xA[q*4+2] = va[p][q].z * mAs[p]; xA[q*4+3] = va[p][q].w * mAs[p];
                xB[q*4+0] = vb[p][q].x * mBs[p]; xB[q*4+1] = vb[p][q].y * mBs[p];
                xB[q*4+2] = vb[p][q].z * mBs[p]; xB[q*4+3] = vb[p][q].w * mBs[p];
            }
            char* tb = (char*)HsF + (size_t)tiles[p] * 528 + gg * 64;
            #pragma unroll
            for (int j = 0; j < 4; j++) {
                uint4 q;
                q.x = h2pack(xA[2*j],     xA[2*j + 1]);
                q.y = h2pack(xB[2*j],     xB[2*j + 1]);
                q.z = h2pack(xA[2*j + 8], xA[2*j + 9]);
                q.w = h2pack(xB[2*j + 8], xB[2*j + 9]);
                *(uint4*)(tb + j * 16) = q;
            }
        }
    }
    __syncthreads();

    const int mq = warp & 3;

    for (int np = (warp >> 2); np < 4; np += 2) {
        float acc[2][8][4];
        #pragma unroll
        for (int im = 0; im < 2; im++)
            #pragma unroll
            for (int in = 0; in < 8; in++)
                #pragma unroll
                for (int c = 0; c < 4; c++) acc[im][in][c] = 0.0f;

        #pragma unroll
        for (int kp = 0; kp < 4; kp++) {
            uint4 bf[8];
            #pragma unroll
            for (int in = 0; in < 8; in++)
                bf[in] = __ldg(&g_W1p[(((np * 8 + in) << 2) + kp) * 32 + lane]);

            const char* xb = (const char*)HsF;
            uint4 ae0 = *(const uint4*)(xb + ((mq*2+0)*8 + 2*kp)     * 528 + lane*16);
            uint4 ao0 = *(const uint4*)(xb + ((mq*2+0)*8 + 2*kp + 1) * 528 + lane*16);
            uint4 ae1 = *(const uint4*)(xb + ((mq*2+1)*8 + 2*kp)     * 528 + lane*16);
            uint4 ao1 = *(const uint4*)(xb + ((mq*2+1)*8 + 2*kp + 1) * 528 + lane*16);

            #pragma unroll
            for (int in = 0; in < 8; in++) {
                mma_f16(acc[0][in][0], acc[0][in][1], acc[0][in][2], acc[0][in][3],
                        ae0.x, ae0.y, ae0.z, ae0.w, bf[in].x, bf[in].y);
                mma_f16(acc[1][in][0], acc[1][in][1], acc[1][in][2], acc[1][in][3],
                        ae1.x, ae1.y, ae1.z, ae1.w, bf[in].x, bf[in].y);
                mma_f16(acc[0][in][0], acc[0][in][1], acc[0][in][2], acc[0][in][3],
                        ao0.x, ao0.y, ao0.z, ao0.w, bf[in].z, bf[in].w);
                mma_f16(acc[1][in][0], acc[1][in][1], acc[1][in][2], acc[1][in][3],
                        ao1.x, ao1.y, ao1.z, ao1.w, bf[in].z, bf[in].w);
            }
        }

        const int nb = np * 64;
        #pragma unroll
        for (int im = 0; im < 2; im++) {
            const int r0 = mq * 32 + im * 16 + g;
            const int n0 = base + r0;
            const int n1 = n0 + 8;
            #pragma unroll
            for (int in = 0; in < 8; in++) {
                const int col0 = nb + in * 8 + 2 * t;
                const bool isA = (col0 < 128);
                const float bb0 = isA ? b1s[col0]     : 0.0f;
                const float bb1 = isA ? b1s[col0 + 1] : 0.0f;
                __half* dst = isA ? g_Ah : g_Bh;
                const int  cc  = isA ? col0 : (col0 - 128);
                if (n0 < n_nodes) {
                    __half2 v = __floats2half2_rn(acc[im][in][0] + bb0,
                                                  acc[im][in][1] + bb1);
                    *(__half2*)(dst + (size_t)n0 * F + cc) = v;
                }
                if (n1 < n_nodes) {
                    __half2 v = __floats2half2_rn(acc[im][in][2] + bb0,
                                                  acc[im][in][3] + bb1);
                    *(__half2*)(dst + (size_t)n1 * F + cc) = v;
                }
            }
        }
    }
}

// ===========================================================================
// Edge kernel: W2 fragments staged to smem via cp.async; hoisted gather.
// smem words: [0,8192) W2s ; [8192, 8192+8448) XsF ; then ss/ds/b2s/w3s/esum
// ===========================================================================
#define W2S_WORDS  8192
#define XSF_BASE   W2S_WORDS
#define MISC_BASE  (XSF_BASE + XSF_WORDS)
#define EDGE_SMEM_B ((MISC_BASE + 5 * 128) * 4)

__global__ void __launch_bounds__(256, 2)
edge_mma_kernel(const int*   __restrict__ src,
                const int*   __restrict__ dst,
                const float* __restrict__ b2,
                const float* __restrict__ W3,
                const float* __restrict__ b3,
                float*       __restrict__ out,
                int n_edges)
{
    extern __shared__ uint32_t sm[];
    uint4*    W2s  = (uint4*)sm;                 // 2048 uint4
    uint32_t* XsF  = sm + XSF_BASE;
    int*      ss   = (int*)(sm + MISC_BASE);
    int*      ds   = ss + 128;
    float*    b2s  = (float*)(ds + 128);
    float*    w3s  = b2s + 128;
    float*    esum = w3s + 128;

    const int tid  = threadIdx.x;
    const int lane = tid & 31;
    const int warp = tid >> 5;
    const int g    = lane >> 2;
    const int t    = lane & 3;
    const int base = blockIdx.x * 128;

    // kick off W2 staging first — overlaps with everything below
    {
        const uint32_t sb = smem_u32(sm);
        const uint4* srcp = g_W2p + tid * 8;
        const uint32_t dstb = sb + tid * 128;
        #pragma unroll
        for (int j = 0; j < 8; j++) cp_async16(dstb + j * 16, srcp + j);
        asm volatile("cp.async.commit_group;");
    }

    if (tid < 128) {
        const int e = base + tid;
        const bool ok = (e < n_edges);
        ss[tid]   = ok ? __ldg(&src[e]) : 0;
        ds[tid]   = ok ? __ldg(&dst[e]) : 0;
        b2s[tid]  = __ldg(&b2[tid]);
        w3s[tid]  = __ldg(&W3[tid]);
        esum[tid] = __ldg(&b3[0]);
    }
    __syncthreads();

    // producer: hoisted half2 gather (8 LDG.128), then combine + STS
    {
        uint4 rAa[2][2], rAb[2][2], rBa[2][2], rBb[2][2];   // [p][half]
        int tiles[2];
        float mAs[2], mBs[2];
        #pragma unroll
        for (int p = 0; p < 2; p++) {
            const int tile = p * 32 + warp * 4 + (lane & 3);
            tiles[p] = tile;
            const int gg = lane >> 2;
            const int mi = tile >> 3;
            const int kc = (tile & 7) * 16;
            const int rA = mi * 16 + gg;
            const int rB = rA + 8;
            mAs[p] = ((base + rA) < n_edges) ? 1.0f : 0.0f;
            mBs[p] = ((base + rB) < n_edges) ? 1.0f : 0.0f;
            const uint4* paA = (const uint4*)(g_Ah + (size_t)ss[rA] * F + kc);
            const uint4* pbA = (const uint4*)(g_Bh + (size_t)ds[rA] * F + kc);
            const uint4* paB = (const uint4*)(g_Ah + (size_t)ss[rB] * F + kc);
            const uint4* pbB = (const uint4*)(g_Bh + (size_t)ds[rB] * F + kc);
            rAa[p][0] = __ldg(paA); rAa[p][1] = __ldg(paA + 1);
            rAb[p][0] = __ldg(pbA); rAb[p][1] = __ldg(pbA + 1);
            rBa[p][0] = __ldg(paB); rBa[p][1] = __ldg(paB + 1);
            rBb[p][0] = __ldg(pbB); rBb[p][1] = __ldg(pbB + 1);
        }
        #pragma unroll
        for (int p = 0; p < 2; p++) {
            const int gg = lane >> 2;
            const __half2 mA = __float2half2_rn(mAs[p]);
            const __half2 mB = __float2half2_rn(mBs[p]);
            __half2 pA[8], pB[8];
            pA[0] = combh2(rAa[p][0].x, rAb[p][0].x, mA);
            pA[1] = combh2(rAa[p][0].y, rAb[p][0].y, mA);
            pA[2] = combh2(rAa[p][0].z, rAb[p][0].z, mA);
            pA[3] = combh2(rAa[p][0].w, rAb[p][0].w, mA);
            pA[4] = combh2(rAa[p][1].x, rAb[p][1].x, mA);
            pA[5] = combh2(rAa[p][1].y, rAb[p][1].y, mA);
            pA[6] = combh2(rAa[p][1].z, rAb[p][1].z, mA);
            pA[7] = combh2(rAa[p][1].w, rAb[p][1].w, mA);
            pB[0] = combh2(rBa[p][0].x, rBb[p][0].x, mB);
            pB[1] = combh2(rBa[p][0].y, rBb[p][0].y, mB);
            pB[2] = combh2(rBa[p][0].z, rBb[p][0].z, mB);
            pB[3] = combh2(rBa[p][0].w, rBb[p][0].w, mB);
            pB[4] = combh2(rBa[p][1].x, rBb[p][1].x, mB);
            pB[5] = combh2(rBa[p][1].y, rBb[p][1].y, mB);
            pB[6] = combh2(rBa[p][1].z, rBb[p][1].z, mB);
            pB[7] = combh2(rBa[p][1].w, rBb[p][1].w, mB);

            char* tb = (char*)XsF + (size_t)tiles[p] * 528 + gg * 64;
            #pragma unroll
            for (int j = 0; j < 4; j++) {
                uint4 q;
                q.x = h2u(pA[j]);     q.y = h2u(pB[j]);
                q.z = h2u(pA[j + 4]); q.w = h2u(pB[j + 4]);
                *(uint4*)(tb + j * 16) = q;
            }
        }
    }
    asm volatile("cp.async.wait_group 0;" ::: "memory");
    __syncthreads();

    const int mq = warp & 3;
    const int nh = warp >> 2;

    float acc[2][8][4];
    #pragma unroll
    for (int im = 0; im < 2; im++)
        #pragma unroll
        for (int in = 0; in < 8; in++)
            #pragma unroll
            for (int c = 0; c < 4; c++) acc[im][in][c] = 0.0f;

    #pragma unroll
    for (int kp = 0; kp < 4; kp++) {
        uint4 bf[8];
        #pragma unroll
        for (int in = 0; in < 8; in++)
            bf[in] = W2s[(((nh * 8 + in) << 2) + kp) * 32 + lane];

        const char* xb = (const char*)XsF;
        uint4 ae0 = *(const uint4*)(xb + ((mq*2+0)*8 + 2*kp)     * 528 + lane*16);
        uint4 ao0 = *(const uint4*)(xb + ((mq*2+0)*8 + 2*kp + 1) * 528 + lane*16);
        uint4 ae1 = *(const uint4*)(xb + ((mq*2+1)*8 + 2*kp)     * 528 + lane*16);
        uint4 ao1 = *(const uint4*)(xb + ((mq*2+1)*8 + 2*kp + 1) * 528 + lane*16);

        #pragma unroll
        for (int in = 0; in < 8; in++) {
            mma_f16(acc[0][in][0], acc[0][in][1], acc[0][in][2], acc[0][in][3],
                    ae0.x, ae0.y, ae0.z, ae0.w, bf[in].x, bf[in].y);
            mma_f16(acc[1][in][0], acc[1][in][1], acc[1][in][2], acc[1][in][3],
                    ae1.x, ae1.y, ae1.z, ae1.w, bf[in].x, bf[in].y);
            mma_f16(acc[0][in][0], acc[0][in][1], acc[0][in][2], acc[0][in][3],
                    ao0.x, ao0.y, ao0.z, ao0.w, bf[in].z, bf[in].w);
            mma_f16(acc[1][in][0], acc[1][in][1], acc[1][in][2], acc[1][in][3],
                    ao1.x, ao1.y, ao1.z, ao1.w, bf[in].z, bf[in].w);
        }
    }

    #pragma unroll
    for (int im = 0; im < 2; im++) {
        float p0 = 0.0f, p1 = 0.0f;
        #pragma unroll
        for (int in = 0; in < 8; in++) {
            const int col0 = nh * 64 + in * 8 + 2 * t;
            const float bb0 = b2s[col0], bb1 = b2s[col0 + 1];
            const float w0  = w3s[col0], w1  = w3s[col0 + 1];
            p0 = fmaf(fmaxf(acc[im][in][0] + bb0, 0.f), w0, p0);
            p0 = fmaf(fmaxf(acc[im][in][1] + bb1, 0.f), w1, p0);
            p1 = fmaf(fmaxf(acc[im][in][2] + bb0, 0.f), w0, p1);
            p1 = fmaf(fmaxf(acc[im][in][3] + bb1, 0.f), w1, p1);
        }
        p0 += __shfl_xor_sync(0xFFFFFFFFu, p0, 1);
        p0 += __shfl_xor_sync(0xFFFFFFFFu, p0, 2);
        p1 += __shfl_xor_sync(0xFFFFFFFFu, p1, 1);
        p1 += __shfl_xor_sync(0xFFFFFFFFu, p1, 2);
        if (t == 0) {
            atomicAdd(&esum[mq * 32 + im * 16 + g],     p0);
            atomicAdd(&esum[mq * 32 + im * 16 + g + 8], p1);
        }
    }
    __syncthreads();

    if (tid < 128) {
        const int e = base + tid;
        if (e < n_edges) out[e] = esum[tid];
    }
}

// ===========================================================================
// launch: inputs: h, src, dst, W1, b1, W2, b2, W3, b3 ; out: [n_edges] f32
// ===========================================================================
extern "C" void kernel_launch(void* const* d_in, const int* in_sizes, int n_in,
                              void* d_out, int out_size)
{
    const float* h   = (const float*)d_in[0];
    const int*   src = (const int*)  d_in[1];
    const int*   dst = (const int*)  d_in[2];
    const float* W1  = (const float*)d_in[3];
    const float* b1  = (const float*)d_in[4];
    const float* W2  = (const float*)d_in[5];
    const float* b2  = (const float*)d_in[6];
    const float* W3  = (const float*)d_in[7];
    const float* b3  = (const float*)d_in[8];
    float*       out = (float*)d_out;

    const int n_nodes = in_sizes[0] / F;
    const int n_edges = in_sizes[1];

    cudaFuncSetAttribute(node_mma_kernel,
                         cudaFuncAttributeMaxDynamicSharedMemorySize, NODE_SMEM_B);
    cudaFuncSetAttribute(edge_mma_kernel,
                         cudaFuncAttributeMaxDynamicSharedMemorySize, EDGE_SMEM_B);

    pack_w2_kernel<<<8, 256>>>(W2);
    pack_w1_kernel<<<16, 256>>>(W1);

    const int gridA = (n_nodes + 127) / 128;
    node_mma_kernel<<<gridA, 256, NODE_SMEM_B>>>(h, b1, n_nodes);

    const int gridB = (n_edges + 127) / 128;
    edge_mma_kernel<<<gridB, 256, EDGE_SMEM_B>>>(src, dst, b2, W3, b3, out, n_edges);
}

// round 10
// speedup vs baseline: 1.0868x; 1.0868x over previous
#include <cuda_runtime.h>
#include <cuda_fp16.h>
#include <cstdint>

#define NN_MAX   100000
#define F        128

// Scratch (fp16): A[n][j] = W1[:,:128]@h[n] + b1 ; B[n][j] = W1[:,128:]@h[n]
__device__ __half g_Ah[NN_MAX * F];
__device__ __half g_Bh[NN_MAX * F];

// Pair-packed fp16 b-fragments for m16n8k16 (row.col):
// entry [ni][kp][lane] (uint4) = { b0(ki=2kp), b1(ki=2kp), b0(ki=2kp+1), b1(ki=2kp+1) }
//   where n = ni*8 + (lane>>2), b0 = h2{W[n][kc+2t],W[n][kc+2t+1]},
//         b1 = h2{W[n][kc+2t+8],W[n][kc+2t+9]}, kc = ki*16, t = lane&3
__device__ uint4 g_W2p[16 * 4 * 32];   // 32 KB
__device__ uint4 g_W1p[32 * 4 * 32];   // 64 KB (256 outs = A||B)

// ---------------------------------------------------------------------------
__device__ __forceinline__ uint32_t h2pack(float lo, float hi) {
    __half2 h = __floats2half2_rn(lo, hi);
    return *reinterpret_cast<uint32_t*>(&h);
}
__device__ __forceinline__ uint32_t h2u(__half2 h) {
    return *reinterpret_cast<uint32_t*>(&h);
}
__device__ __forceinline__ __half2 combh2(uint32_t a, uint32_t b, __half2 m) {
    __half2 ha = *reinterpret_cast<__half2*>(&a);
    __half2 hb = *reinterpret_cast<__half2*>(&b);
    const __half2 z = __float2half2_rn(0.0f);
    return __hmul2(__hmax2(__hadd2(ha, hb), z), m);
}

__device__ __forceinline__ void mma_f16(float& c0, float& c1, float& c2, float& c3,
                                        uint32_t a0, uint32_t a1, uint32_t a2, uint32_t a3,
                                        uint32_t b0, uint32_t b1)
{
    asm volatile(
        "mma.sync.aligned.m16n8k16.row.col.f32.f16.f16.f32 "
        "{%0,%1,%2,%3}, {%4,%5,%6,%7}, {%8,%9}, {%0,%1,%2,%3};\n"
        : "+f"(c0), "+f"(c1), "+f"(c2), "+f"(c3)
        : "r"(a0), "r"(a1), "r"(a2), "r"(a3), "r"(b0), "r"(b1));
}

// ===========================================================================
// Prep kernels: pair-packed fragments
// ===========================================================================
__global__ void pack_w2_kernel(const float* __restrict__ W2)
{
    const int idx  = blockIdx.x * blockDim.x + threadIdx.x;   // 0..2047
    if (idx >= 16 * 4 * 32) return;
    const int lane = idx & 31;
    const int kp   = (idx >> 5) & 3;
    const int ni   = idx >> 7;
    const int g    = lane >> 2;
    const int t    = lane & 3;
    const float* w = W2 + (size_t)(ni * 8 + g) * F + kp * 32;
    uint4 q;
    q.x = h2pack(__ldg(&w[2*t]),      __ldg(&w[2*t + 1]));
    q.y = h2pack(__ldg(&w[2*t + 8]),  __ldg(&w[2*t + 9]));
    q.z = h2pack(__ldg(&w[16 + 2*t]),     __ldg(&w[16 + 2*t + 1]));
    q.w = h2pack(__ldg(&w[16 + 2*t + 8]), __ldg(&w[16 + 2*t + 9]));
    g_W2p[idx] = q;
}

__global__ void pack_w1_kernel(const float* __restrict__ W1)
{
    const int idx  = blockIdx.x * blockDim.x + threadIdx.x;   // 0..4095
    if (idx >= 32 * 4 * 32) return;
    const int lane = idx & 31;
    const int kp   = (idx >> 5) & 3;
    const int ni   = idx >> 7;
    const int g    = lane >> 2;
    const int t    = lane & 3;
    const int j2   = ni * 8 + g;
    const float* w = W1 + (size_t)(j2 & 127) * 256 + ((j2 >> 7) << 7) + kp * 32;
    uint4 q;
    q.x = h2pack(__ldg(&w[2*t]),      __ldg(&w[2*t + 1]));
    q.y = h2pack(__ldg(&w[2*t + 8]),  __ldg(&w[2*t + 9]));
    q.z = h2pack(__ldg(&w[16 + 2*t]),     __ldg(&w[16 + 2*t + 1]));
    q.w = h2pack(__ldg(&w[16 + 2*t + 8]), __ldg(&w[16 + 2*t + 9]));
    g_W1p[idx] = q;
}

// ===========================================================================
// fp16 fragment tile layout: tile = mi*8 + ki (mi 0..7, ki 0..7), stride 528 B
// lane (g,t) uint4 = {h2 row(g) k(2t), h2 row(g+8) k(2t),
//                     h2 row(g) k(2t+8), h2 row(g+8) k(2t+8)}
// ===========================================================================
#define XSF_WORDS   (64 * 132)

// ===========================================================================
// Node kernel: [A|B] = h @ W1^T -> fp16 g_Ah/g_Bh
// ===========================================================================
#define NODE_SMEM_B ((XSF_WORDS + 128) * 4 + 16)

__global__ void __launch_bounds__(256, 2)
node_mma_kernel(const float* __restrict__ h,
                const float* __restrict__ b1,
                int n_nodes)
{
    extern __shared__ uint32_t sm[];
    uint32_t* HsF = sm;
    float*    b1s = (float*)(sm + XSF_WORDS);

    const int tid  = threadIdx.x;
    const int lane = tid & 31;
    const int warp = tid >> 5;
    const int g    = lane >> 2;
    const int t    = lane & 3;
    const int base = blockIdx.x * 128;

    if (tid < 128) b1s[tid] = __ldg(&b1[tid]);

    // producer: hoisted loads (8 float4-pairs), then pack + STS
    {
        float4 va[2][4], vb[2][4];
        int tiles[2];
        float mAs[2], mBs[2];
        #pragma unroll
        for (int p = 0; p < 2; p++) {
            const int tile = p * 32 + warp * 4 + (lane & 3);
            tiles[p] = tile;
            const int gg = lane >> 2;
            const int mi = tile >> 3;
            const int kc = (tile & 7) * 16;
            const int rA = mi * 16 + gg;
            const int rB = rA + 8;
            mAs[p] = ((base + rA) < n_nodes) ? 1.0f : 0.0f;
            mBs[p] = ((base + rB) < n_nodes) ? 1.0f : 0.0f;
            const int nA = ((base + rA) < n_nodes) ? (base + rA) : 0;
            const int nB = ((base + rB) < n_nodes) ? (base + rB) : 0;
            const float4* pa = (const float4*)(h + (size_t)nA * F + kc);
            const float4* pb = (const float4*)(h + (size_t)nB * F + kc);
            #pragma unroll
            for (int q = 0; q < 4; q++) { va[p][q] = __ldg(pa + q); vb[p][q] = __ldg(pb + q); }
        }
        #pragma unroll
        for (int p = 0; p < 2; p++) {
            const int gg = lane >> 2;
            float xA[16], xB[16];
            #pragma unroll
            for (int q = 0; q < 4; q++) {
                xA[q*4+0] = va[p][q].x * mAs[p]; xA[q*4+1] = va[p][q].y * mAs[p];
                xA[q*4+2] = va[p][q].z * mAs[p]; xA[q*4+3] = va[p][q].w * mAs[p];
                xB[q*4+0] = vb[p][q].x * mBs[p]; xB[q*4+1] = vb[p][q].y * mBs[p];
                xB[q*4+2] = vb[p][q].z * mBs[p]; xB[q*4+3] = vb[p][q].w * mBs[p];
            }
            char* tb = (char*)HsF + (size_t)tiles[p] * 528 + gg * 64;
            #pragma unroll
            for (int j = 0; j < 4; j++) {
                uint4 q;
                q.x = h2pack(xA[2*j],     xA[2*j + 1]);
                q.y = h2pack(xB[2*j],     xB[2*j + 1]);
                q.z = h2pack(xA[2*j + 8], xA[2*j + 9]);
                q.w = h2pack(xB[2*j + 8], xB[2*j + 9]);
                *(uint4*)(tb + j * 16) = q;
            }
        }
    }
    __syncthreads();

    const int mq = warp & 3;

    for (int np = (warp >> 2); np < 4; np += 2) {
        float acc[2][8][4];
        #pragma unroll
        for (int im = 0; im < 2; im++)
            #pragma unroll
            for (int in = 0; in < 8; in++)
                #pragma unroll
                for (int c = 0; c < 4; c++) acc[im][in][c] = 0.0f;

        #pragma unroll
        for (int kp = 0; kp < 4; kp++) {
            uint4 bf[8];
            #pragma unroll
            for (int in = 0; in < 8; in++)
                bf[in] = __ldg(&g_W1p[(((np * 8 + in) << 2) + kp) * 32 + lane]);

            const char* xb = (const char*)HsF;
            uint4 ae0 = *(const uint4*)(xb + ((mq*2+0)*8 + 2*kp)     * 528 + lane*16);
            uint4 ao0 = *(const uint4*)(xb + ((mq*2+0)*8 + 2*kp + 1) * 528 + lane*16);
            uint4 ae1 = *(const uint4*)(xb + ((mq*2+1)*8 + 2*kp)     * 528 + lane*16);
            uint4 ao1 = *(const uint4*)(xb + ((mq*2+1)*8 + 2*kp + 1) * 528 + lane*16);

            #pragma unroll
            for (int in = 0; in < 8; in++) {
                mma_f16(acc[0][in][0], acc[0][in][1], acc[0][in][2], acc[0][in][3],
                        ae0.x, ae0.y, ae0.z, ae0.w, bf[in].x, bf[in].y);
                mma_f16(acc[1][in][0], acc[1][in][1], acc[1][in][2], acc[1][in][3],
                        ae1.x, ae1.y, ae1.z, ae1.w, bf[in].x, bf[in].y);
                mma_f16(acc[0][in][0], acc[0][in][1], acc[0][in][2], acc[0][in][3],
                        ao0.x, ao0.y, ao0.z, ao0.w, bf[in].z, bf[in].w);
                mma_f16(acc[1][in][0], acc[1][in][1], acc[1][in][2], acc[1][in][3],
                        ao1.x, ao1.y, ao1.z, ao1.w, bf[in].z, bf[in].w);
            }
        }

        const int nb = np * 64;
        #pragma unroll
        for (int im = 0; im < 2; im++) {
            const int r0 = mq * 32 + im * 16 + g;
            const int n0 = base + r0;
            const int n1 = n0 + 8;
            #pragma unroll
            for (int in = 0; in < 8; in++) {
                const int col0 = nb + in * 8 + 2 * t;
                const bool isA = (col0 < 128);
                const float bb0 = isA ? b1s[col0]     : 0.0f;
                const float bb1 = isA ? b1s[col0 + 1] : 0.0f;
                __half* dst = isA ? g_Ah : g_Bh;
                const int  cc  = isA ? col0 : (col0 - 128);
                if (n0 < n_nodes) {
                    __half2 v = __floats2half2_rn(acc[im][in][0] + bb0,
                                                  acc[im][in][1] + bb1);
                    *(__half2*)(dst + (size_t)n0 * F + cc) = v;
                }
                if (n1 < n_nodes) {
                    __half2 v = __floats2half2_rn(acc[im][in][2] + bb0,
                                                  acc[im][in][3] + bb1);
                    *(__half2*)(dst + (size_t)n1 * F + cc) = v;
                }
            }
        }
    }
}

// ===========================================================================
// Edge kernel: gather hoisted; B fragments via LDG.128 from g_W2p (L1-resident)
// ===========================================================================
#define EDGE_SMEM_B ((XSF_WORDS + 128 * 5) * 4 + 16)

__global__ void __launch_bounds__(256, 2)
edge_mma_kernel(const int*   __restrict__ src,
                const int*   __restrict__ dst,
                const float* __restrict__ b2,
                const float* __restrict__ W3,
                const float* __restrict__ b3,
                float*       __restrict__ out,
                int n_edges)
{
    extern __shared__ uint32_t sm[];
    uint32_t* XsF  = sm;
    int*      ss   = (int*)(sm + XSF_WORDS);
    int*      ds   = ss + 128;
    float*    b2s  = (float*)(ds + 128);
    float*    w3s  = b2s + 128;
    float*    esum = w3s + 128;

    const int tid  = threadIdx.x;
    const int lane = tid & 31;
    const int warp = tid >> 5;
    const int g    = lane >> 2;
    const int t    = lane & 3;
    const int base = blockIdx.x * 128;

    if (tid < 128) {
        const int e = base + tid;
        const bool ok = (e < n_edges);
        ss[tid]   = ok ? __ldg(&src[e]) : 0;
        ds[tid]   = ok ? __ldg(&dst[e]) : 0;
        b2s[tid]  = __ldg(&b2[tid]);
        w3s[tid]  = __ldg(&W3[tid]);
        esum[tid] = __ldg(&b3[0]);
    }
    __syncthreads();

    // producer: hoisted half2 gather (8 LDG.128), then combine + STS
    {
        uint4 rAa[2][2], rAb[2][2], rBa[2][2], rBb[2][2];
        int tiles[2];
        float mAs[2], mBs[2];
        #pragma unroll
        for (int p = 0; p < 2; p++) {
            const int tile = p * 32 + warp * 4 + (lane & 3);
            tiles[p] = tile;
            const int gg = lane >> 2;
            const int mi = tile >> 3;
            const int kc = (tile & 7) * 16;
            const int rA = mi * 16 + gg;
            const int rB = rA + 8;
            mAs[p] = ((base + rA) < n_edges) ? 1.0f : 0.0f;
            mBs[p] = ((base + rB) < n_edges) ? 1.0f : 0.0f;
            const uint4* paA = (const uint4*)(g_Ah + (size_t)ss[rA] * F + kc);
            const uint4* pbA = (const uint4*)(g_Bh + (size_t)ds[rA] * F + kc);
            const uint4* paB = (const uint4*)(g_Ah + (size_t)ss[rB] * F + kc);
            const uint4* pbB = (const uint4*)(g_Bh + (size_t)ds[rB] * F + kc);
            rAa[p][0] = __ldg(paA); rAa[p][1] = __ldg(paA + 1);
            rAb[p][0] = __ldg(pbA); rAb[p][1] = __ldg(pbA + 1);
            rBa[p][0] = __ldg(paB); rBa[p][1] = __ldg(paB + 1);
            rBb[p][0] = __ldg(pbB); rBb[p][1] = __ldg(pbB + 1);
        }
        #pragma unroll
        for (int p = 0; p < 2; p++) {
            const int gg = lane >> 2;
            const __half2 mA = __float2half2_rn(mAs[p]);
            const __half2 mB = __float2half2_rn(mBs[p]);
            __half2 pA[8], pB[8];
            pA[0] = combh2(rAa[p][0].x, rAb[p][0].x, mA);
            pA[1] = combh2(rAa[p][0].y, rAb[p][0].y, mA);
            pA[2] = combh2(rAa[p][0].z, rAb[p][0].z, mA);
            pA[3] = combh2(rAa[p][0].w, rAb[p][0].w, mA);
            pA[4] = combh2(rAa[p][1].x, rAb[p][1].x, mA);
            pA[5] = combh2(rAa[p][1].y, rAb[p][1].y, mA);
            pA[6] = combh2(rAa[p][1].z, rAb[p][1].z, mA);
            pA[7] = combh2(rAa[p][1].w, rAb[p][1].w, mA);
            pB[0] = combh2(rBa[p][0].x, rBb[p][0].x, mB);
            pB[1] = combh2(rBa[p][0].y, rBb[p][0].y, mB);
            pB[2] = combh2(rBa[p][0].z, rBb[p][0].z, mB);
            pB[3] = combh2(rBa[p][0].w, rBb[p][0].w, mB);
            pB[4] = combh2(rBa[p][1].x, rBb[p][1].x, mB);
            pB[5] = combh2(rBa[p][1].y, rBb[p][1].y, mB);
            pB[6] = combh2(rBa[p][1].z, rBb[p][1].z, mB);
            pB[7] = combh2(rBa[p][1].w, rBb[p][1].w, mB);

            char* tb = (char*)XsF + (size_t)tiles[p] * 528 + gg * 64;
            #pragma unroll
            for (int j = 0; j < 4; j++) {
                uint4 q;
                q.x = h2u(pA[j]);     q.y = h2u(pB[j]);
                q.z = h2u(pA[j + 4]); q.w = h2u(pB[j + 4]);
                *(uint4*)(tb + j * 16) = q;
            }
        }
    }
    __syncthreads();

    const int mq = warp & 3;
    const int nh = warp >> 2;

    float acc[2][8][4];
    #pragma unroll
    for (int im = 0; im < 2; im++)
        #pragma unroll
        for (int in = 0; in < 8; in++)
            #pragma unroll
            for (int c = 0; c < 4; c++) acc[im][in][c] = 0.0f;

    #pragma unroll
    for (int kp = 0; kp < 4; kp++) {
        uint4 bf[8];
        #pragma unroll
        for (int in = 0; in < 8; in++)
            bf[in] = __ldg(&g_W2p[(((nh * 8 + in) << 2) + kp) * 32 + lane]);

        const char* xb = (const char*)XsF;
        uint4 ae0 = *(const uint4*)(xb + ((mq*2+0)*8 + 2*kp)     * 528 + lane*16);
        uint4 ao0 = *(const uint4*)(xb + ((mq*2+0)*8 + 2*kp + 1) * 528 + lane*16);
        uint4 ae1 = *(const uint4*)(xb + ((mq*2+1)*8 + 2*kp)     * 528 + lane*16);
        uint4 ao1 = *(const uint4*)(xb + ((mq*2+1)*8 + 2*kp + 1) * 528 + lane*16);

        #pragma unroll
        for (int in = 0; in < 8; in++) {
            mma_f16(acc[0][in][0], acc[0][in][1], acc[0][in][2], acc[0][in][3],
                    ae0.x, ae0.y, ae0.z, ae0.w, bf[in].x, bf[in].y);
            mma_f16(acc[1][in][0], acc[1][in][1], acc[1][in][2], acc[1][in][3],
                    ae1.x, ae1.y, ae1.z, ae1.w, bf[in].x, bf[in].y);
            mma_f16(acc[0][in][0], acc[0][in][1], acc[0][in][2], acc[0][in][3],
                    ao0.x, ao0.y, ao0.z, ao0.w, bf[in].z, bf[in].w);
            mma_f16(acc[1][in][0], acc[1][in][1], acc[1][in][2], acc[1][in][3],
                    ao1.x, ao1.y, ao1.z, ao1.w, bf[in].z, bf[in].w);
        }
    }

    #pragma unroll
    for (int im = 0; im < 2; im++) {
        float p0 = 0.0f, p1 = 0.0f;
        #pragma unroll
        for (int in = 0; in < 8; in++) {
            const int col0 = nh * 64 + in * 8 + 2 * t;
            const float bb0 = b2s[col0], bb1 = b2s[col0 + 1];
            const float w0  = w3s[col0], w1  = w3s[col0 + 1];
            p0 = fmaf(fmaxf(acc[im][in][0] + bb0, 0.f), w0, p0);
            p0 = fmaf(fmaxf(acc[im][in][1] + bb1, 0.f), w1, p0);
            p1 = fmaf(fmaxf(acc[im][in][2] + bb0, 0.f), w0, p1);
            p1 = fmaf(fmaxf(acc[im][in][3] + bb1, 0.f), w1, p1);
        }
        p0 += __shfl_xor_sync(0xFFFFFFFFu, p0, 1);
        p0 += __shfl_xor_sync(0xFFFFFFFFu, p0, 2);
        p1 += __shfl_xor_sync(0xFFFFFFFFu, p1, 1);
        p1 += __shfl_xor_sync(0xFFFFFFFFu, p1, 2);
        if (t == 0) {
            atomicAdd(&esum[mq * 32 + im * 16 + g],     p0);
            atomicAdd(&esum[mq * 32 + im * 16 + g + 8], p1);
        }
    }
    __syncthreads();

    if (tid < 128) {
        const int e = base + tid;
        if (e < n_edges) out[e] = esum[tid];
    }
}

// ===========================================================================
// launch: inputs: h, src, dst, W1, b1, W2, b2, W3, b3 ; out: [n_edges] f32
// ===========================================================================
extern "C" void kernel_launch(void* const* d_in, const int* in_sizes, int n_in,
                              void* d_out, int out_size)
{
    const float* h   = (const float*)d_in[0];
    const int*   src = (const int*)  d_in[1];
    const int*   dst = (const int*)  d_in[2];
    const float* W1  = (const float*)d_in[3];
    const float* b1  = (const float*)d_in[4];
    const float* W2  = (const float*)d_in[5];
    const float* b2  = (const float*)d_in[6];
    const float* W3  = (const float*)d_in[7];
    const float* b3  = (const float*)d_in[8];
    float*       out = (float*)d_out;

    const int n_nodes = in_sizes[0] / F;
    const int n_edges = in_sizes[1];

    cudaFuncSetAttribute(node_mma_kernel,
                         cudaFuncAttributeMaxDynamicSharedMemorySize, NODE_SMEM_B);
    cudaFuncSetAttribute(edge_mma_kernel,
                         cudaFuncAttributeMaxDynamicSharedMemorySize, EDGE_SMEM_B);

    pack_w2_kernel<<<8, 256>>>(W2);
    pack_w1_kernel<<<16, 256>>>(W1);

    const int gridA = (n_nodes + 127) / 128;
    node_mma_kernel<<<gridA, 256, NODE_SMEM_B>>>(h, b1, n_nodes);

    const int gridB = (n_edges + 127) / 128;
    edge_mma_kernel<<<gridB, 256, EDGE_SMEM_B>>>(src, dst, b2, W3, b3, out, n_edges);
}

// round 11
// speedup vs baseline: 1.1801x; 1.0859x over previous
#include <cuda_runtime.h>
#include <cuda_fp16.h>
#include <cstdint>

#define NN_MAX   100000
#define F        128

// Scratch (fp16): A[n][j] = W1[:,:128]@h[n] + b1 ; B[n][j] = W1[:,128:]@h[n]
__device__ __half g_Ah[NN_MAX * F];
__device__ __half g_Bh[NN_MAX * F];

// fp16 b-fragments for m16n8k16 (row.col)  [R8 layout, uint2 per k-step]
//   b0 = {W[n][kc+2t], W[n][kc+2t+1]}, b1 = {W[n][kc+2t+8], W[n][kc+2t+9]},
//   n = ni*8 + (lane>>2), kc = ki*16
__device__ uint2 g_W2f[16 * 8 * 32];
__device__ uint2 g_W1f[32 * 8 * 32];

// ---------------------------------------------------------------------------
__device__ __forceinline__ uint32_t h2pack(float lo, float hi) {
    __half2 h = __floats2half2_rn(lo, hi);
    return *reinterpret_cast<uint32_t*>(&h);
}
__device__ __forceinline__ uint32_t h2u(__half2 h) {
    return *reinterpret_cast<uint32_t*>(&h);
}
__device__ __forceinline__ __half2 combh2(uint32_t a, uint32_t b, __half2 m) {
    __half2 ha = *reinterpret_cast<__half2*>(&a);
    __half2 hb = *reinterpret_cast<__half2*>(&b);
    const __half2 z = __float2half2_rn(0.0f);
    return __hmul2(__hmax2(__hadd2(ha, hb), z), m);
}

__device__ __forceinline__ void mma_f16(float& c0, float& c1, float& c2, float& c3,
                                        uint32_t a0, uint32_t a1, uint32_t a2, uint32_t a3,
                                        uint32_t b0, uint32_t b1)
{
    asm volatile(
        "mma.sync.aligned.m16n8k16.row.col.f32.f16.f16.f32 "
        "{%0,%1,%2,%3}, {%4,%5,%6,%7}, {%8,%9}, {%0,%1,%2,%3};\n"
        : "+f"(c0), "+f"(c1), "+f"(c2), "+f"(c3)
        : "r"(a0), "r"(a1), "r"(a2), "r"(a3), "r"(b0), "r"(b1));
}

// ===========================================================================
// Prep kernels (R8 form)
// ===========================================================================
__global__ void pack_w2_kernel(const float* __restrict__ W2)
{
    const int idx  = blockIdx.x * blockDim.x + threadIdx.x;
    if (idx >= 16 * 8 * 32) return;
    const int lane = idx & 31;
    const int ki   = (idx >> 5) & 7;
    const int ni   = idx >> 8;
    const int g    = lane >> 2;
    const int t    = lane & 3;
    const float* w = W2 + (size_t)(ni * 8 + g) * F + ki * 16;
    uint2 v;
    v.x = h2pack(__ldg(&w[2 * t]),     __ldg(&w[2 * t + 1]));
    v.y = h2pack(__ldg(&w[2 * t + 8]), __ldg(&w[2 * t + 9]));
    g_W2f[idx] = v;
}

__global__ void pack_w1_kernel(const float* __restrict__ W1)
{
    const int idx  = blockIdx.x * blockDim.x + threadIdx.x;
    if (idx >= 32 * 8 * 32) return;
    const int lane = idx & 31;
    const int ki   = (idx >> 5) & 7;
    const int ni   = idx >> 8;
    const int g    = lane >> 2;
    const int t    = lane & 3;
    const int j2   = ni * 8 + g;
    const float* w = W1 + (size_t)(j2 & 127) * 256 + ((j2 >> 7) << 7) + ki * 16;
    uint2 v;
    v.x = h2pack(__ldg(&w[2 * t]),     __ldg(&w[2 * t + 1]));
    v.y = h2pack(__ldg(&w[2 * t + 8]), __ldg(&w[2 * t + 9]));
    g_W1f[idx] = v;
}

// ===========================================================================
// Node kernel (exact R8): [A|B] = h @ W1^T -> fp16 g_Ah/g_Bh
// fp16 fragment tile layout: tile = mi*8 + ki, stride 528 B
// ===========================================================================
#define XSF_WORDS   (64 * 132)
#define NODE_SMEM_B ((XSF_WORDS + 128) * 4 + 16)

__global__ void __launch_bounds__(256, 2)
node_mma_kernel(const float* __restrict__ h,
                const float* __restrict__ b1,
                int n_nodes)
{
    extern __shared__ uint32_t sm[];
    uint32_t* HsF = sm;
    float*    b1s = (float*)(sm + XSF_WORDS);

    const int tid  = threadIdx.x;
    const int lane = tid & 31;
    const int warp = tid >> 5;
    const int g    = lane >> 2;
    const int t    = lane & 3;
    const int base = blockIdx.x * 128;

    if (tid < 128) b1s[tid] = __ldg(&b1[tid]);

    #pragma unroll
    for (int p = 0; p < 2; p++) {
        const int tile = p * 32 + warp * 4 + (lane & 3);
        const int gg   = lane >> 2;
        const int mi   = tile >> 3;
        const int kc   = (tile & 7) * 16;
        const int rA   = mi * 16 + gg;
        const int rB   = rA + 8;
        const float mA = ((base + rA) < n_nodes) ? 1.0f : 0.0f;
        const float mB = ((base + rB) < n_nodes) ? 1.0f : 0.0f;
        const int  nA  = ((base + rA) < n_nodes) ? (base + rA) : 0;
        const int  nB  = ((base + rB) < n_nodes) ? (base + rB) : 0;

        float xA[16], xB[16];
        {
            const float4* pa = (const float4*)(h + (size_t)nA * F + kc);
            const float4* pb = (const float4*)(h + (size_t)nB * F + kc);
            #pragma unroll
            for (int q = 0; q < 4; q++) {
                float4 a = __ldg(pa + q);
                float4 b = __ldg(pb + q);
                xA[q*4+0] = a.x * mA; xA[q*4+1] = a.y * mA;
                xA[q*4+2] = a.z * mA; xA[q*4+3] = a.w * mA;
                xB[q*4+0] = b.x * mB; xB[q*4+1] = b.y * mB;
                xB[q*4+2] = b.z * mB; xB[q*4+3] = b.w * mB;
            }
        }

        char* tb = (char*)HsF + (size_t)tile * 528 + gg * 64;
        #pragma unroll
        for (int j = 0; j < 4; j++) {
            uint4 q;
            q.x = h2pack(xA[2*j],     xA[2*j + 1]);
            q.y = h2pack(xB[2*j],     xB[2*j + 1]);
            q.z = h2pack(xA[2*j + 8], xA[2*j + 9]);
            q.w = h2pack(xB[2*j + 8], xB[2*j + 9]);
            *(uint4*)(tb + j * 16) = q;
        }
    }
    __syncthreads();

    const int mq = warp & 3;

    for (int np = (warp >> 2); np < 4; np += 2) {
        float acc[2][8][4];
        #pragma unroll
        for (int im = 0; im < 2; im++)
            #pragma unroll
            for (int in = 0; in < 8; in++)
                #pragma unroll
                for (int c = 0; c < 4; c++) acc[im][in][c] = 0.0f;

        #pragma unroll
        for (int ki = 0; ki < 8; ki++) {
            uint2 bf[8];
            #pragma unroll
            for (int in = 0; in < 8; in++)
                bf[in] = __ldg(&g_W1f[(((np * 8 + in) << 3) + ki) * 32 + lane]);

            uint4 aq0 = *(const uint4*)((const char*)HsF +
                         (size_t)((mq * 2 + 0) * 8 + ki) * 528 + lane * 16);
            uint4 aq1 = *(const uint4*)((const char*)HsF +
                         (size_t)((mq * 2 + 1) * 8 + ki) * 528 + lane * 16);

            #pragma unroll
            for (int in = 0; in < 8; in++) {
                mma_f16(acc[0][in][0], acc[0][in][1], acc[0][in][2], acc[0][in][3],
                        aq0.x, aq0.y, aq0.z, aq0.w, bf[in].x, bf[in].y);
                mma_f16(acc[1][in][0], acc[1][in][1], acc[1][in][2], acc[1][in][3],
                        aq1.x, aq1.y, aq1.z, aq1.w, bf[in].x, bf[in].y);
            }
        }

        const int nb = np * 64;
        #pragma unroll
        for (int im = 0; im < 2; im++) {
            const int r0 = mq * 32 + im * 16 + g;
            const int n0 = base + r0;
            const int n1 = n0 + 8;
            #pragma unroll
            for (int in = 0; in < 8; in++) {
                const int col0 = nb + in * 8 + 2 * t;
                const bool isA = (col0 < 128);
                const float bb0 = isA ? b1s[col0]     : 0.0f;
                const float bb1 = isA ? b1s[col0 + 1] : 0.0f;
                __half* dst = isA ? g_Ah : g_Bh;
                const int  cc  = isA ? col0 : (col0 - 128);
                if (n0 < n_nodes) {
                    __half2 v = __floats2half2_rn(acc[im][in][0] + bb0,
                                                  acc[im][in][1] + bb1);
                    *(__half2*)(dst + (size_t)n0 * F + cc) = v;
                }
                if (n1 < n_nodes) {
                    __half2 v = __floats2half2_rn(acc[im][in][2] + bb0,
                                                  acc[im][in][3] + bb1);
                    *(__half2*)(dst + (size_t)n1 * F + cc) = v;
                }
            }
        }
    }
}

// ===========================================================================
// Edge kernel: 64 edges / 128 threads / 4 blocks per SM.
// Warp (mq = warp&1, nh = warp>>1): 32m x 64n, K=128. Same per-edge traffic
// as R8 but 4 independent phase-streams per SM.
// XsF2: 32 tiles (mi 0..3, ki 0..7), stride 528 B.
// ===========================================================================
#define XSF2_WORDS  (32 * 132)
#define EDGE_SMEM_B ((XSF2_WORDS + 64 * 3 + 128 * 2) * 4 + 16)

__global__ void __launch_bounds__(128, 4)
edge_mma_kernel(const int*   __restrict__ src,
                const int*   __restrict__ dst,
                const float* __restrict__ b2,
                const float* __restrict__ W3,
                const float* __restrict__ b3,
                float*       __restrict__ out,
                int n_edges)
{
    extern __shared__ uint32_t sm[];
    uint32_t* XsF  = sm;
    int*      ss   = (int*)(sm + XSF2_WORDS);
    int*      ds   = ss + 64;
    float*    b2s  = (float*)(ds + 64);
    float*    w3s  = b2s + 128;
    float*    esum = w3s + 128;

    const int tid  = threadIdx.x;
    const int lane = tid & 31;
    const int warp = tid >> 5;
    const int g    = lane >> 2;
    const int t    = lane & 3;
    const int base = blockIdx.x * 64;

    {
        b2s[tid] = __ldg(&b2[tid]);
        w3s[tid] = __ldg(&W3[tid]);
        if (tid < 64) {
            const int e = base + tid;
            const bool ok = (e < n_edges);
            ss[tid]   = ok ? __ldg(&src[e]) : 0;
            ds[tid]   = ok ? __ldg(&dst[e]) : 0;
            esum[tid] = __ldg(&b3[0]);
        }
    }
    __syncthreads();

    // producer: 2 tasks/thread over 32 tiles x 8 gg
    #pragma unroll
    for (int p = 0; p < 2; p++) {
        const int tile = p * 16 + warp * 4 + (lane & 3);   // 0..31
        const int gg   = lane >> 2;
        const int mi   = tile >> 3;                        // 0..3
        const int kc   = (tile & 7) * 16;
        const int rA   = mi * 16 + gg;
        const int rB   = rA + 8;
        const __half2 mA = __float2half2_rn(((base + rA) < n_edges) ? 1.0f : 0.0f);
        const __half2 mB = __float2half2_rn(((base + rB) < n_edges) ? 1.0f : 0.0f);

        __half2 pA[8], pB[8];
        {
            const uint4* pa = (const uint4*)(g_Ah + (size_t)ss[rA] * F + kc);
            const uint4* pb = (const uint4*)(g_Bh + (size_t)ds[rA] * F + kc);
            uint4 a0 = __ldg(pa), a1 = __ldg(pa + 1);
            uint4 b0 = __ldg(pb), b1 = __ldg(pb + 1);
            pA[0] = combh2(a0.x, b0.x, mA); pA[1] = combh2(a0.y, b0.y, mA);
            pA[2] = combh2(a0.z, b0.z, mA); pA[3] = combh2(a0.w, b0.w, mA);
            pA[4] = combh2(a1.x, b1.x, mA); pA[5] = combh2(a1.y, b1.y, mA);
            pA[6] = combh2(a1.z, b1.z, mA); pA[7] = combh2(a1.w, b1.w, mA);
        }
        {
            const uint4* pa = (const uint4*)(g_Ah + (size_t)ss[rB] * F + kc);
            const uint4* pb = (const uint4*)(g_Bh + (size_t)ds[rB] * F + kc);
            uint4 a0 = __ldg(pa), a1 = __ldg(pa + 1);
            uint4 b0 = __ldg(pb), b1 = __ldg(pb + 1);
            pB[0] = combh2(a0.x, b0.x, mB); pB[1] = combh2(a0.y, b0.y, mB);
            pB[2] = combh2(a0.z, b0.z, mB); pB[3] = combh2(a0.w, b0.w, mB);
            pB[4] = combh2(a1.x, b1.x, mB); pB[5] = combh2(a1.y, b1.y, mB);
            pB[6] = combh2(a1.z, b1.z, mB); pB[7] = combh2(a1.w, b1.w, mB);
        }

        char* tb = (char*)XsF + (size_t)tile * 528 + gg * 64;
        #pragma unroll
        for (int j = 0; j < 4; j++) {
            uint4 q;
            q.x = h2u(pA[j]);     q.y = h2u(pB[j]);
            q.z = h2u(pA[j + 4]); q.w = h2u(pB[j + 4]);
            *(uint4*)(tb + j * 16) = q;
        }
    }
    __syncthreads();

    const int mq = warp & 1;
    const int nh = warp >> 1;

    float acc[2][8][4];
    #pragma unroll
    for (int im = 0; im < 2; im++)
        #pragma unroll
        for (int in = 0; in < 8; in++)
            #pragma unroll
            for (int c = 0; c < 4; c++) acc[im][in][c] = 0.0f;

    #pragma unroll
    for (int ki = 0; ki < 8; ki++) {
        uint2 bf[8];
        #pragma unroll
        for (int in = 0; in < 8; in++)
            bf[in] = __ldg(&g_W2f[(((nh * 8 + in) << 3) + ki) * 32 + lane]);

        uint4 aq0 = *(const uint4*)((const char*)XsF +
                     (size_t)((mq * 2 + 0) * 8 + ki) * 528 + lane * 16);
        uint4 aq1 = *(const uint4*)((const char*)XsF +
                     (size_t)((mq * 2 + 1) * 8 + ki) * 528 + lane * 16);

        #pragma unroll
        for (int in = 0; in < 8; in++) {
            mma_f16(acc[0][in][0], acc[0][in][1], acc[0][in][2], acc[0][in][3],
                    aq0.x, aq0.y, aq0.z, aq0.w, bf[in].x, bf[in].y);
            mma_f16(acc[1][in][0], acc[1][in][1], acc[1][in][2], acc[1][in][3],
                    aq1.x, aq1.y, aq1.z, aq1.w, bf[in].x, bf[in].y);
        }
    }

    #pragma unroll
    for (int im = 0; im < 2; im++) {
        float p0 = 0.0f, p1 = 0.0f;
        #pragma unroll
        for (int in = 0; in < 8; in++) {
            const int col0 = nh * 64 + in * 8 + 2 * t;
            const float bb0 = b2s[col0], bb1 = b2s[col0 + 1];
            const float w0  = w3s[col0], w1  = w3s[col0 + 1];
            p0 = fmaf(fmaxf(acc[im][in][0] + bb0, 0.f), w0, p0);
            p0 = fmaf(fmaxf(acc[im][in][1] + bb1, 0.f), w1, p0);
            p1 = fmaf(fmaxf(acc[im][in][2] + bb0, 0.f), w0, p1);
            p1 = fmaf(fmaxf(acc[im][in][3] + bb1, 0.f), w1, p1);
        }
        p0 += __shfl_xor_sync(0xFFFFFFFFu, p0, 1);
        p0 += __shfl_xor_sync(0xFFFFFFFFu, p0, 2);
        p1 += __shfl_xor_sync(0xFFFFFFFFu, p1, 1);
        p1 += __shfl_xor_sync(0xFFFFFFFFu, p1, 2);
        if (t == 0) {
            atomicAdd(&esum[mq * 32 + im * 16 + g],     p0);
            atomicAdd(&esum[mq * 32 + im * 16 + g + 8], p1);
        }
    }
    __syncthreads();

    if (tid < 64) {
        const int e = base + tid;
        if (e < n_edges) out[e] = esum[tid];
    }
}

// ===========================================================================
// launch: inputs: h, src, dst, W1, b1, W2, b2, W3, b3 ; out: [n_edges] f32
// ===========================================================================
extern "C" void kernel_launch(void* const* d_in, const int* in_sizes, int n_in,
                              void* d_out, int out_size)
{
    const float* h   = (const float*)d_in[0];
    const int*   src = (const int*)  d_in[1];
    const int*   dst = (const int*)  d_in[2];
    const float* W1  = (const float*)d_in[3];
    const float* b1  = (const float*)d_in[4];
    const float* W2  = (const float*)d_in[5];
    const float* b2  = (const float*)d_in[6];
    const float* W3  = (const float*)d_in[7];
    const float* b3  = (const float*)d_in[8];
    float*       out = (float*)d_out;

    const int n_nodes = in_sizes[0] / F;
    const int n_edges = in_sizes[1];

    cudaFuncSetAttribute(node_mma_kernel,
                         cudaFuncAttributeMaxDynamicSharedMemorySize, NODE_SMEM_B);
    cudaFuncSetAttribute(edge_mma_kernel,
                         cudaFuncAttributeMaxDynamicSharedMemorySize, EDGE_SMEM_B);

    pack_w2_kernel<<<16, 256>>>(W2);
    pack_w1_kernel<<<32, 256>>>(W1);

    const int gridA = (n_nodes + 127) / 128;
    node_mma_kernel<<<gridA, 256, NODE_SMEM_B>>>(h, b1, n_nodes);

    const int gridB = (n_edges + 63) / 64;
    edge_mma_kernel<<<gridB, 128, EDGE_SMEM_B>>>(src, dst, b2, W3, b3, out, n_edges);
}